// round 1
// baseline (speedup 1.0000x reference)
#include <cuda_runtime.h>
#include <cstdint>

// Segment mean-pooling over sorted segment ids.
//   feats:        [B, S, H] float32
//   segment_ids:  [B, S]    int32, sorted non-decreasing per row, values in [0, G)
// Output: grouped [B, G, H] float32 (+ optionally counts [B, G] appended, as float values)
//
// G is fixed by the problem definition.
#define GROUPS 1024
#define MAX_BG 32768  // >= B*(G+1); B=8 -> 8200 needed

// Scratch: group start offsets per (b, g), plus sentinel start[b][G] = S.
__device__ int g_start_scratch[MAX_BG];

// ---------------------------------------------------------------------------
// Kernel 1: mark group boundaries.
// For token s in row b with id cur and previous id prev (-1 at s==0),
// every group g in (prev, cur] starts at s. The last token also closes the
// tail: groups (cur, G] start at S.
// ---------------------------------------------------------------------------
__global__ void mark_boundaries_kernel(const int* __restrict__ seg,
                                       int B, int S) {
    int idx = blockIdx.x * blockDim.x + threadIdx.x;
    if (idx >= B * S) return;
    int b = idx / S;
    int s = idx - b * S;

    int cur  = seg[idx];
    int prev = (s == 0) ? -1 : seg[idx - 1];

    int* row = g_start_scratch + b * (GROUPS + 1);
    for (int g = prev + 1; g <= cur; ++g) row[g] = s;
    if (s == S - 1) {
        for (int g = cur + 1; g <= GROUPS; ++g) row[g] = S;
    }
}

// ---------------------------------------------------------------------------
// Kernel 2: one CTA per (b, g). threads = H/4 (float4 lanes across H).
// Sum contiguous token range [s0, s1), multiply by 1/count, store.
// ---------------------------------------------------------------------------
__global__ void __launch_bounds__(128)
group_mean_kernel(const float* __restrict__ feats,
                  float* __restrict__ out,
                  float* __restrict__ counts_out,  // may be nullptr
                  int B, int S, int H) {
    const int g = blockIdx.x;
    const int b = blockIdx.y;

    const int* row = g_start_scratch + b * (GROUPS + 1);
    const int s0 = row[g];
    const int s1 = row[g + 1];
    const int cnt = s1 - s0;

    const int h4 = H >> 2;  // float4 lanes (128 for H=512)
    const float4* base = reinterpret_cast<const float4*>(
        feats + (size_t)b * S * H);

    float4 acc = make_float4(0.f, 0.f, 0.f, 0.f);
    int t = threadIdx.x;

    // Unrolled-by-2 accumulation for memory-level parallelism.
    int s = s0;
    for (; s + 1 < s1; s += 2) {
        float4 v0 = base[(size_t)s * h4 + t];
        float4 v1 = base[(size_t)(s + 1) * h4 + t];
        acc.x += v0.x + v1.x;
        acc.y += v0.y + v1.y;
        acc.z += v0.z + v1.z;
        acc.w += v0.w + v1.w;
    }
    if (s < s1) {
        float4 v0 = base[(size_t)s * h4 + t];
        acc.x += v0.x; acc.y += v0.y; acc.z += v0.z; acc.w += v0.w;
    }

    const float inv = (cnt > 0) ? (1.0f / (float)cnt) : 0.0f;
    acc.x *= inv; acc.y *= inv; acc.z *= inv; acc.w *= inv;

    float4* obase = reinterpret_cast<float4*>(
        out + ((size_t)b * GROUPS + g) * H);
    obase[t] = acc;

    if (counts_out != nullptr && threadIdx.x == 0) {
        counts_out[(size_t)b * GROUPS + g] = (float)cnt;
    }
}

extern "C" void kernel_launch(void* const* d_in, const int* in_sizes, int n_in,
                              void* d_out, int out_size) {
    const float* feats = (const float*)d_in[0];
    const int*   seg   = (const int*)d_in[1];

    const int BS = in_sizes[1];            // B*S
    const int H  = in_sizes[0] / BS;       // 512

    // Determine B and whether counts are appended to the output buffer.
    long long gh = (long long)GROUPS * H;
    int B;
    float* counts_out = nullptr;
    if ((long long)out_size % (gh + GROUPS) == 0 &&
        (long long)out_size / (gh + GROUPS) == BS / 8192) {
        B = (int)((long long)out_size / (gh + GROUPS));
        counts_out = (float*)d_out + (long long)B * gh;
    } else if ((long long)out_size % gh == 0) {
        B = (int)((long long)out_size / gh);
        if ((long long)B * gh != (long long)out_size) {
            // has trailing counts region
            B = (int)((long long)out_size / (gh + GROUPS));
            counts_out = (float*)d_out + (long long)B * gh;
        }
    } else {
        B = (int)((long long)out_size / (gh + GROUPS));
        counts_out = (float*)d_out + (long long)B * gh;
    }
    const int S = BS / B;

    // Kernel 1: boundary marking.
    {
        int threads = 256;
        int blocks = (BS + threads - 1) / threads;
        mark_boundaries_kernel<<<blocks, threads>>>(seg, B, S);
    }

    // Kernel 2: per-(b,g) contiguous mean.
    {
        dim3 grid(GROUPS, B);
        int threads = H >> 2;  // 128 for H=512
        group_mean_kernel<<<grid, threads>>>(feats, (float*)d_out,
                                             counts_out, B, S, H);
    }
}

// round 2
// speedup vs baseline: 1.0513x; 1.0513x over previous
#include <cuda_runtime.h>
#include <cstdint>

// Segment mean-pooling over sorted segment ids.
//   feats:        [B, S, H] float32
//   segment_ids:  [B, S]    int32, sorted non-decreasing per row, values in [0, G)
// Output: grouped [B, G, H] float32, counts [B, G] appended as float values.
#define GROUPS 1024
#define MAX_BG 32768  // >= B*(G+1); B=8 -> 8200 needed

__device__ int g_start_scratch[MAX_BG];

// ---------------------------------------------------------------------------
// Kernel 1: mark group boundaries.
// ---------------------------------------------------------------------------
__global__ void mark_boundaries_kernel(const int* __restrict__ seg,
                                       int B, int S) {
    int idx = blockIdx.x * blockDim.x + threadIdx.x;
    if (idx >= B * S) return;
    int b = idx / S;
    int s = idx - b * S;

    int cur  = seg[idx];
    int prev = (s == 0) ? -1 : seg[idx - 1];

    int* row = g_start_scratch + b * (GROUPS + 1);
    for (int g = prev + 1; g <= cur; ++g) row[g] = s;
    if (s == S - 1) {
        for (int g = cur + 1; g <= GROUPS; ++g) row[g] = S;
    }
}

// ---------------------------------------------------------------------------
// Kernel 2: one CTA per (b, g), 128 threads = H/4 float4 lanes.
// Unroll-by-4 with independent accumulators -> MLP_eff = 4 outstanding
// LDG.128 per thread. Streaming cache hints (ldcs/stcs): data touched once.
// ---------------------------------------------------------------------------
__global__ void __launch_bounds__(128)
group_mean_kernel(const float* __restrict__ feats,
                  float* __restrict__ out,
                  float* __restrict__ counts_out,
                  int B, int S, int H) {
    const int g = blockIdx.x;
    const int b = blockIdx.y;

    const int* row = g_start_scratch + b * (GROUPS + 1);
    const int s0 = row[g];
    const int s1 = row[g + 1];
    const int cnt = s1 - s0;

    const int h4 = H >> 2;  // 128 float4 lanes for H=512
    const float4* base = reinterpret_cast<const float4*>(
        feats + (size_t)b * S * H) + threadIdx.x;

    float4 a0 = make_float4(0.f, 0.f, 0.f, 0.f);
    float4 a1 = make_float4(0.f, 0.f, 0.f, 0.f);
    float4 a2 = make_float4(0.f, 0.f, 0.f, 0.f);
    float4 a3 = make_float4(0.f, 0.f, 0.f, 0.f);

    int s = s0;
    // Main loop: 4 independent loads in flight before any dependent add.
    for (; s + 3 < s1; s += 4) {
        float4 v0 = __ldcs(&base[(size_t)(s + 0) * h4]);
        float4 v1 = __ldcs(&base[(size_t)(s + 1) * h4]);
        float4 v2 = __ldcs(&base[(size_t)(s + 2) * h4]);
        float4 v3 = __ldcs(&base[(size_t)(s + 3) * h4]);
        a0.x += v0.x; a0.y += v0.y; a0.z += v0.z; a0.w += v0.w;
        a1.x += v1.x; a1.y += v1.y; a1.z += v1.z; a1.w += v1.w;
        a2.x += v2.x; a2.y += v2.y; a2.z += v2.z; a2.w += v2.w;
        a3.x += v3.x; a3.y += v3.y; a3.z += v3.z; a3.w += v3.w;
    }
    // Remainder (0-3 rows), still independent accumulators.
    if (s + 0 < s1) {
        float4 v = __ldcs(&base[(size_t)(s + 0) * h4]);
        a0.x += v.x; a0.y += v.y; a0.z += v.z; a0.w += v.w;
    }
    if (s + 1 < s1) {
        float4 v = __ldcs(&base[(size_t)(s + 1) * h4]);
        a1.x += v.x; a1.y += v.y; a1.z += v.z; a1.w += v.w;
    }
    if (s + 2 < s1) {
        float4 v = __ldcs(&base[(size_t)(s + 2) * h4]);
        a2.x += v.x; a2.y += v.y; a2.z += v.z; a2.w += v.w;
    }

    const float inv = (cnt > 0) ? (1.0f / (float)cnt) : 0.0f;
    float4 r;
    r.x = (a0.x + a1.x + a2.x + a3.x) * inv;
    r.y = (a0.y + a1.y + a2.y + a3.y) * inv;
    r.z = (a0.z + a1.z + a2.z + a3.z) * inv;
    r.w = (a0.w + a1.w + a2.w + a3.w) * inv;

    float4* obase = reinterpret_cast<float4*>(
        out + ((size_t)b * GROUPS + g) * H);
    __stcs(&obase[threadIdx.x], r);

    if (counts_out != nullptr && threadIdx.x == 0) {
        counts_out[(size_t)b * GROUPS + g] = (float)cnt;
    }
}

extern "C" void kernel_launch(void* const* d_in, const int* in_sizes, int n_in,
                              void* d_out, int out_size) {
    const float* feats = (const float*)d_in[0];
    const int*   seg   = (const int*)d_in[1];

    const int BS = in_sizes[1];            // B*S
    const int H  = in_sizes[0] / BS;       // 512

    long long gh = (long long)GROUPS * H;
    int B;
    float* counts_out = nullptr;
    if ((long long)out_size % (gh + GROUPS) == 0 &&
        (long long)out_size / (gh + GROUPS) == BS / 8192) {
        B = (int)((long long)out_size / (gh + GROUPS));
        counts_out = (float*)d_out + (long long)B * gh;
    } else if ((long long)out_size % gh == 0) {
        B = (int)((long long)out_size / gh);
        if ((long long)B * gh != (long long)out_size) {
            B = (int)((long long)out_size / (gh + GROUPS));
            counts_out = (float*)d_out + (long long)B * gh;
        }
    } else {
        B = (int)((long long)out_size / (gh + GROUPS));
        counts_out = (float*)d_out + (long long)B * gh;
    }
    const int S = BS / B;

    {
        int threads = 256;
        int blocks = (BS + threads - 1) / threads;
        mark_boundaries_kernel<<<blocks, threads>>>(seg, B, S);
    }
    {
        dim3 grid(GROUPS, B);
        int threads = H >> 2;
        group_mean_kernel<<<grid, threads>>>(feats, (float*)d_out,
                                             counts_out, B, S, H);
    }
}